// round 11
// baseline (speedup 1.0000x reference)
#include <cuda_runtime.h>
#include <cuda_bf16.h>
#include <stdint.h>
#include <math.h>

#define BATCH 2048
#define NP 32
#define DD 6
#define NOBS 17
#define HID 256
#define NSTEPS 10
#define LRATE 0.1f
#define CLIP_LIM 1.0f
#define LOG_NP1 3.49650756f

// ---- pre-baked B-operand images (bf16 hi/lo pairs packed in u32) ----------
// Layout: chunk c holds k in [32c,32c+32); within chunk: row n (0..255) of 16
// u32 units (unit = bf16 pair (k,k+1)); unit index swizzled:
//   idx = c*4096 + n*16 + (kp ^ (((n>>1)&3)<<2)),  kp = (k%32)/2
__device__ unsigned g_BfH[32768], g_BfL[32768];   // fwd  B[n][k] = W2[k][n]
__device__ unsigned g_BbH[32768], g_BbL[32768];   // bwd  B[n][k] = W2[n][k]
__device__ unsigned g_W1H[4096],  g_W1L[4096];    // z1   B[n][k] = W1[k][n], K=32 pad
__device__ float g_W1xT[HID * DD];
__device__ unsigned short g_W3H[HID], g_W3L[HID];

__device__ __forceinline__ void split2(float v0, float v1, unsigned& hi, unsigned& lo) {
    __nv_bfloat16 h0 = __float2bfloat16(v0), h1 = __float2bfloat16(v1);
    float r0 = v0 - __bfloat162float(h0), r1 = v1 - __bfloat162float(h1);
    hi = (unsigned)__bfloat16_as_ushort(h0) | ((unsigned)__bfloat16_as_ushort(h1) << 16);
    lo = (unsigned)__bfloat16_as_ushort(__float2bfloat16(r0)) |
         ((unsigned)__bfloat16_as_ushort(__float2bfloat16(r1)) << 16);
}

__device__ __forceinline__ unsigned su32(const void* p) {
    unsigned a;
    asm("{ .reg .u64 t; cvta.to.shared.u64 t, %1; cvt.u32.u64 %0, t; }" : "=r"(a) : "l"(p));
    return a;
}
#define CPA16(d, s) asm volatile("cp.async.cg.shared.global [%0], [%1], 16;" :: "r"(d), "l"(s))
#define CPC()       asm volatile("cp.async.commit_group;" ::: "memory")
#define CPW0()      asm volatile("cp.async.wait_group 0;" ::: "memory")

__device__ __forceinline__ void mma16816(float* c, const unsigned* a, unsigned b0, unsigned b1) {
    asm volatile(
        "mma.sync.aligned.m16n8k16.row.col.f32.bf16.bf16.f32 "
        "{%0,%1,%2,%3}, {%4,%5,%6,%7}, {%8,%9}, {%0,%1,%2,%3};"
        : "+f"(c[0]), "+f"(c[1]), "+f"(c[2]), "+f"(c[3])
        : "r"(a[0]), "r"(a[1]), "r"(a[2]), "r"(a[3]), "r"(b0), "r"(b1));
}

// ---- prep: bake weight images --------------------------------------------
__global__ void prep_kernel(const float* __restrict__ W1, const float* __restrict__ W2,
                            const float* __restrict__ W3) {
    const int t = blockIdx.x * 256 + threadIdx.x;   // 128 blocks x 256
    const int n = t >> 7, kp = t & 127, k = kp * 2;
    const int idx = (kp >> 4) * 4096 + n * 16 + ((kp & 15) ^ (((n >> 1) & 3) << 2));
    unsigned hi, lo;
    split2(W2[k * 256 + n], W2[(k + 1) * 256 + n], hi, lo);   // fwd
    g_BfH[idx] = hi; g_BfL[idx] = lo;
    split2(W2[n * 256 + k], W2[n * 256 + k + 1], hi, lo);     // bwd
    g_BbH[idx] = hi; g_BbL[idx] = lo;
    if (kp < 16) {
        float v0 = (k < 23) ? W1[k * 256 + n] : 0.0f;
        float v1 = (k + 1 < 23) ? W1[(k + 1) * 256 + n] : 0.0f;
        split2(v0, v1, hi, lo);
        const int i2 = n * 16 + (kp ^ (((n >> 1) & 3) << 2));
        g_W1H[i2] = hi; g_W1L[i2] = lo;
    }
    if (kp < 6) g_W1xT[n * 6 + kp] = W1[(17 + kp) * 256 + n];
    if (kp == 0) {
        __nv_bfloat16 h = __float2bfloat16(W3[n]);
        g_W3H[n] = __bfloat16_as_ushort(h);
        g_W3L[n] = __bfloat16_as_ushort(__float2bfloat16(W3[n] - __bfloat162float(h)));
    }
}

// ---- shared memory --------------------------------------------------------
// A images: [m 0..127][unit kp 0..127], idx = m*128 + (kp ^ ((m&7)<<2))
struct __align__(16) SM {
    unsigned Ah[16384], Al[16384];          // 64KB + 64KB
    unsigned Bh[2][4096], Bl[2][4096];      // double-buffered 16KB chunks
    float X[2][128 * 6];
    float s[128 * 6];
    float scratch[128 * 6 * 4];             // spart
    float W1xT[256 * 6];
    float b1[256], b2[256];
    float logp[128];
    float gamma[4];
    unsigned short W3H[256], W3L[256];
};

extern __shared__ char smraw[];

__device__ __forceinline__ void issue_chunk(SM* sm, int buf,
                                            const unsigned* __restrict__ gBh,
                                            const unsigned* __restrict__ gBl,
                                            int ch, int tid) {
    const unsigned dH = su32(sm->Bh[buf]), dL = su32(sm->Bl[buf]);
    const char* sH = (const char*)(gBh + ch * 4096);
    const char* sL = (const char*)(gBl + ch * 4096);
    for (int i = tid; i < 1024; i += 512) {
        CPA16(dH + i * 16, sH + i * 16);
        CPA16(dL + i * 16, sL + i * 16);
    }
    CPC();
}

// Double-buffered GEMM: M=128, N=256, K = 32*NCHUNK, bf16x3.
// Single barrier per chunk: wait(ch) -> bar -> issue(ch+1) -> compute(ch).
// Buffer reuse is safe: readers of buf[(ch+1)&1] (chunk ch-1) passed this
// iteration's barrier before the new issue starts writing it.
template <int NCHUNK>
__device__ __forceinline__ void gemm_mma(SM* sm, const unsigned* __restrict__ gBh,
                                         const unsigned* __restrict__ gBl,
                                         float acc[2][8][4], int m0, int n0,
                                         int lane, int tid) {
#pragma unroll
    for (int i = 0; i < 2; i++)
#pragma unroll
        for (int j = 0; j < 8; j++)
#pragma unroll
            for (int e = 0; e < 4; e++) acc[i][j][e] = 0.0f;
    const int swA = (lane >> 2) << 2;

    issue_chunk(sm, 0, gBh, gBl, 0, tid);
    for (int ch = 0; ch < NCHUNK; ch++) {
        CPW0();                     // chunk ch landed (own copies)
        __syncthreads();            // all copies visible; prior readers done
        if (ch + 1 < NCHUNK) issue_chunk(sm, (ch + 1) & 1, gBh, gBl, ch + 1, tid);
        const unsigned* Bhc = sm->Bh[ch & 1];
        const unsigned* Blc = sm->Bl[ch & 1];
#pragma unroll
        for (int pass = 0; pass < 3; pass++) {
            const unsigned* A = (pass == 2) ? sm->Al : sm->Ah;
            const unsigned* B = (pass == 1) ? Blc : Bhc;
#pragma unroll
            for (int ks = 0; ks < 2; ks++) {
                const int kpb = ch * 16 + ks * 8 + (lane & 3);
                const int kpl = ks * 8 + (lane & 3);
                unsigned af[2][4];
#pragma unroll
                for (int mt = 0; mt < 2; mt++) {
                    const int r = m0 + mt * 16 + (lane >> 2);
                    af[mt][0] = A[r * 128 + (kpb ^ swA)];
                    af[mt][1] = A[(r + 8) * 128 + (kpb ^ swA)];
                    af[mt][2] = A[r * 128 + ((kpb + 4) ^ swA)];
                    af[mt][3] = A[(r + 8) * 128 + ((kpb + 4) ^ swA)];
                }
#pragma unroll
                for (int nt = 0; nt < 8; nt++) {
                    const int n = n0 + nt * 8 + (lane >> 2);
                    const int swb = ((n >> 1) & 3) << 2;
                    const unsigned b0 = B[n * 16 + (kpl ^ swb)];
                    const unsigned b1 = B[n * 16 + ((kpl + 4) ^ swb)];
                    mma16816(acc[0][nt], af[0], b0, b1);
                    mma16816(acc[1][nt], af[1], b0, b1);
                }
            }
        }
    }
    __syncthreads();                // A-image readers done before epilogue writes
}

__global__ void __launch_bounds__(512, 1) svgd_kernel(
    const float* __restrict__ g_obs, const float* __restrict__ g_a,
    const float* __restrict__ g_b1, const float* __restrict__ g_b2,
    float* __restrict__ g_out)
{
    SM* sm = (SM*)smraw;
    const int tid = threadIdx.x, bx = blockIdx.x;
    const int warp = tid >> 5, lane = tid & 31;
    const int m0 = (warp & 3) * 32;          // warp row tile
    const int wN = warp >> 2;                // warp col group
    const int n0 = wN * 64;
    const int swA = (lane >> 2) << 2;

    // ---- prologue ---------------------------------------------------------
    if (tid < 256) {
        sm->b1[tid] = g_b1[tid];
        sm->b2[tid] = g_b2[tid];
        sm->W3H[tid] = g_W3H[tid];
        sm->W3L[tid] = g_W3L[tid];
    }
    for (int i = tid; i < 1536; i += 512) sm->W1xT[i] = g_W1xT[i];
    for (int i = tid; i < 768; i += 512) sm->X[0][i] = g_a[bx * 768 + i];
    if (tid < 128) sm->logp[tid] = 0.0f;
    __syncthreads();

    int cur = 0;
    float acc[2][8][4];
    unsigned mk[2];

    for (int step = 0; step < NSTEPS; step++) {
        // ---- build z1 A image: obs + X + pad (kp 0..15) -----------------
        for (int idx = tid; idx < 128 * 16; idx += 512) {
            const int row = idx >> 4, kp = idx & 15, k0 = kp * 2;
            float v0, v1;
            v0 = (k0 < NOBS) ? g_obs[(bx * 128 + row) * NOBS + k0]
               : (k0 < 23)   ? sm->X[cur][row * 6 + k0 - NOBS] : 0.0f;
            const int k1 = k0 + 1;
            v1 = (k1 < NOBS) ? g_obs[(bx * 128 + row) * NOBS + k1]
               : (k1 < 23)   ? sm->X[cur][row * 6 + k1 - NOBS] : 0.0f;
            unsigned hi, lo;
            split2(v0, v1, hi, lo);
            const int o = row * 128 + (kp ^ ((row & 7) << 2));
            sm->Ah[o] = hi; sm->Al[o] = lo;
        }
        // (gemm's first barrier orders these writes before MMA reads)

        // ---- z1 GEMM + epilogue: h1 = relu(z1+b1), mask, split ----------
        gemm_mma<1>(sm, g_W1H, g_W1L, acc, m0, n0, lane, tid);
        mk[0] = 0u; mk[1] = 0u;
#pragma unroll
        for (int mt = 0; mt < 2; mt++) {
            const int rA = m0 + mt * 16 + (lane >> 2);
#pragma unroll
            for (int nt = 0; nt < 8; nt++) {
                const int cA = n0 + nt * 8 + ((lane & 3) << 1);
                const int kp = cA >> 1;
                float h0 = fmaxf(acc[mt][nt][0] + sm->b1[cA], 0.0f);
                float h1 = fmaxf(acc[mt][nt][1] + sm->b1[cA + 1], 0.0f);
                float h2 = fmaxf(acc[mt][nt][2] + sm->b1[cA], 0.0f);
                float h3 = fmaxf(acc[mt][nt][3] + sm->b1[cA + 1], 0.0f);
                if (h0 > 0.0f) mk[mt] |= 1u << (nt * 4 + 0);
                if (h1 > 0.0f) mk[mt] |= 1u << (nt * 4 + 1);
                if (h2 > 0.0f) mk[mt] |= 1u << (nt * 4 + 2);
                if (h3 > 0.0f) mk[mt] |= 1u << (nt * 4 + 3);
                unsigned hi, lo;
                split2(h0, h1, hi, lo);
                int o = rA * 128 + (kp ^ swA);
                sm->Ah[o] = hi; sm->Al[o] = lo;
                split2(h2, h3, hi, lo);
                o = (rA + 8) * 128 + (kp ^ swA);
                sm->Ah[o] = hi; sm->Al[o] = lo;
            }
        }

        // ---- fwd GEMM (z2) + epilogue: dz2 = (z2+b2>0)*W3 ---------------
        gemm_mma<8>(sm, g_BfH, g_BfL, acc, m0, n0, lane, tid);
#pragma unroll
        for (int mt = 0; mt < 2; mt++) {
            const int rA = m0 + mt * 16 + (lane >> 2);
#pragma unroll
            for (int nt = 0; nt < 8; nt++) {
                const int cA = n0 + nt * 8 + ((lane & 3) << 1);
                const int kp = cA >> 1;
                const bool s0 = acc[mt][nt][0] + sm->b2[cA] > 0.0f;
                const bool s1 = acc[mt][nt][1] + sm->b2[cA + 1] > 0.0f;
                const bool s2 = acc[mt][nt][2] + sm->b2[cA] > 0.0f;
                const bool s3 = acc[mt][nt][3] + sm->b2[cA + 1] > 0.0f;
                const unsigned h0 = s0 ? sm->W3H[cA] : 0, h1 = s1 ? sm->W3H[cA + 1] : 0;
                const unsigned h2 = s2 ? sm->W3H[cA] : 0, h3 = s3 ? sm->W3H[cA + 1] : 0;
                const unsigned l0 = s0 ? sm->W3L[cA] : 0, l1 = s1 ? sm->W3L[cA + 1] : 0;
                const unsigned l2 = s2 ? sm->W3L[cA] : 0, l3 = s3 ? sm->W3L[cA + 1] : 0;
                int o = rA * 128 + (kp ^ swA);
                sm->Ah[o] = h0 | (h1 << 16); sm->Al[o] = l0 | (l1 << 16);
                o = (rA + 8) * 128 + (kp ^ swA);
                sm->Ah[o] = h2 | (h3 << 16); sm->Al[o] = l2 | (l3 << 16);
            }
        }

        // ---- bwd GEMM (dz1) + epilogue: mask + fold score matmul --------
        gemm_mma<8>(sm, g_BbH, g_BbL, acc, m0, n0, lane, tid);
        {
            float sp[4][6];
#pragma unroll
            for (int s = 0; s < 4; s++)
#pragma unroll
                for (int d = 0; d < 6; d++) sp[s][d] = 0.0f;
#pragma unroll
            for (int mt = 0; mt < 2; mt++)
#pragma unroll
                for (int nt = 0; nt < 8; nt++)
#pragma unroll
                    for (int e = 0; e < 4; e++) {
                        const float v = ((mk[mt] >> (nt * 4 + e)) & 1u)
                                            ? acc[mt][nt][e] : 0.0f;
                        const int c = n0 + nt * 8 + ((lane & 3) << 1) + (e & 1);
                        const int s = mt * 2 + (e >> 1);
                        const float* w = &sm->W1xT[c * 6];
#pragma unroll
                        for (int d = 0; d < 6; d++) sp[s][d] = fmaf(v, w[d], sp[s][d]);
                    }
#pragma unroll
            for (int s = 0; s < 4; s++)
#pragma unroll
                for (int d = 0; d < 6; d++) {
                    sp[s][d] += __shfl_xor_sync(0xFFFFFFFFu, sp[s][d], 1);
                    sp[s][d] += __shfl_xor_sync(0xFFFFFFFFu, sp[s][d], 2);
                }
            if ((lane & 3) == 0) {
#pragma unroll
                for (int s = 0; s < 4; s++) {
                    const int row = m0 + (s >> 1) * 16 + (s & 1) * 8 + (lane >> 2);
#pragma unroll
                    for (int d = 0; d < 6; d++)
                        sm->scratch[(row * 6 + d) * 4 + wN] = sp[s][d];
                }
            }
        }
        __syncthreads();
        for (int i = tid; i < 768; i += 512)
            sm->s[i] = sm->scratch[4 * i] + sm->scratch[4 * i + 1] +
                       sm->scratch[4 * i + 2] + sm->scratch[4 * i + 3];

        // ---- median: warp-local register bitonic sort (warps 0-3) -------
        // 512 elems = 496 upper-tri dists + inf pad; elem e = r*32 + lane.
        // Multiset median idx 511 of 1024 -> sorted-pairs idx 239 = (r7,l15).
        if (warp < 4) {
            const int g = warp;
            const float* Xg = &sm->X[cur][g * 192];
            float v[16];
#pragma unroll
            for (int r = 0; r < 16; r++) {
                const int e = r * 32 + lane;
                float val = __int_as_float(0x7f800000);
                if (e < 496) {
                    // triangular index -> (i,j): off(i) = i*(63-i)/2
                    int i = (int)((63.0f - sqrtf(3969.0f - 8.0f * (float)e)) * 0.5f);
                    int off = (i * (63 - i)) >> 1;
                    if (e < off) { i--; off = (i * (63 - i)) >> 1; }
                    else {
                        const int off2 = ((i + 1) * (62 - i)) >> 1;
                        if (e >= off2) { i++; off = off2; }
                    }
                    const int j = i + 1 + (e - off);
                    float ds = 0.0f;
#pragma unroll
                    for (int d = 0; d < 6; d++) {
                        const float dx = Xg[i * 6 + d] - Xg[j * 6 + d];
                        ds = fmaf(dx, dx, ds);
                    }
                    val = ds;
                }
                v[r] = val;
            }
#pragma unroll
            for (int k = 2; k <= 512; k <<= 1) {
#pragma unroll
                for (int j = k >> 1; j > 0; j >>= 1) {
                    if (j >= 32) {
                        const int rr = j >> 5;
#pragma unroll
                        for (int r = 0; r < 16; r++)
                            if (!(r & rr)) {
                                const int rp = r | rr;
                                const bool asc = ((r & (k >> 5)) == 0);
                                const float a = v[r], b = v[rp];
                                const float mn = fminf(a, b), mx = fmaxf(a, b);
                                v[r]  = asc ? mn : mx;
                                v[rp] = asc ? mx : mn;
                            }
                    } else {
#pragma unroll
                        for (int r = 0; r < 16; r++) {
                            const bool asc = (k >= 32) ? ((r & (k >> 5)) == 0)
                                                       : ((lane & k) == 0);
                            const float pv = __shfl_xor_sync(0xFFFFFFFFu, v[r], j);
                            const bool lower = ((lane & j) == 0);
                            const float mn = fminf(v[r], pv), mx = fmaxf(v[r], pv);
                            v[r] = (lower == asc) ? mn : mx;
                        }
                    }
                }
            }
            if (lane == 15) {
                const float hm = v[7] / (2.0f * LOG_NP1);
                sm->gamma[g] = 1.0f / (1e-8f + 2.0f * hm);
            }
        }
        __syncthreads();

        // ---- RBF phi / logp (4 warps per batch, 8 rows per warp) --------
        {
            const int g = warp >> 2, rb = (warp & 3) * 8;
            const float gamma = sm->gamma[g];
            const float* Xg = &sm->X[cur][g * 192];
            float* Xn = &sm->X[cur ^ 1][g * 192];
            const float* sg = &sm->s[g * 192];
            for (int ii = 0; ii < 8; ii++) {
                const int i = rb + ii, j = lane;
                float dx[6], red[8], ds = 0.0f, dsq = 0.0f;
#pragma unroll
                for (int d = 0; d < 6; d++) {
                    dx[d] = Xg[i * 6 + d] - Xg[j * 6 + d];
                    dsq = fmaf(dx[d], dx[d], dsq);
                }
                const float kap = __expf(-gamma * dsq);
#pragma unroll
                for (int d = 0; d < 6; d++) {
                    red[d] = kap * (sg[j * 6 + d] + 2.0f * gamma * dx[d]);
                    ds = fmaf(dx[d], sg[j * 6 + d], ds);
                }
                red[6] = -2.0f * gamma * kap * ds;
                red[7] = 2.0f * gamma * dsq * kap - 6.0f * kap;
#pragma unroll
                for (int q = 0; q < 8; q++)
#pragma unroll
                    for (int off = 16; off > 0; off >>= 1)
                        red[q] += __shfl_xor_sync(0xFFFFFFFFu, red[q], off);
                if (lane == 0) {
#pragma unroll
                    for (int d = 0; d < 6; d++) {
                        float xn = Xg[i * 6 + d] + LRATE * (red[d] * (1.0f / 32.0f));
                        Xn[i * 6 + d] = fminf(fmaxf(xn, -CLIP_LIM), CLIP_LIM);
                    }
                    const float l4 = red[6] * (1.0f / 32.0f);
                    const float l5 = -2.0f * gamma * (red[7] * (1.0f / 32.0f));
                    sm->logp[g * 32 + i] -= LRATE * (l4 + l5);
                }
            }
        }
        cur ^= 1;
        __syncthreads();
    }

    // ---- outputs ----------------------------------------------------------
    for (int i = tid; i < 768; i += 512) g_out[bx * 768 + i] = sm->X[cur][i];
    if (tid < 128) g_out[BATCH * NP * DD + bx * 128 + tid] = sm->logp[tid];
}

// ---------------------------------------------------------------------------
extern "C" void kernel_launch(void* const* d_in, const int* in_sizes, int n_in,
                              void* d_out, int out_size) {
    const float* obs = (const float*)d_in[0];
    const float* a   = (const float*)d_in[1];
    const float* W1  = (const float*)d_in[2];
    const float* b1  = (const float*)d_in[3];
    const float* W2  = (const float*)d_in[4];
    const float* b2  = (const float*)d_in[5];
    const float* W3  = (const float*)d_in[6];
    // d_in[7] = b3: unused (does not affect gradients/outputs)
    float* out = (float*)d_out;

    prep_kernel<<<128, 256>>>(W1, W2, W3);
    cudaFuncSetAttribute(svgd_kernel, cudaFuncAttributeMaxDynamicSharedMemorySize,
                         (int)sizeof(SM));
    svgd_kernel<<<512, 512, sizeof(SM)>>>(obs, a, b1, b2, out);
}

// round 12
// speedup vs baseline: 1.2881x; 1.2881x over previous
#include <cuda_runtime.h>
#include <cuda_fp16.h>
#include <stdint.h>
#include <math.h>

#define BATCH 2048
#define NP 32
#define DD 6
#define NOBS 17
#define HID 256
#define NSTEPS 10
#define LRATE 0.1f
#define CLIP_LIM 1.0f
#define LOG_NP1 3.49650756f

// ---- pre-baked B-operand images (fp16 pairs packed in u32, single image) --
// Layout: chunk c holds k in [32c,32c+32); within chunk: row n (0..255) of 16
// u32 units (unit = fp16 pair (k,k+1)); unit index swizzled:
//   idx = c*4096 + n*16 + (kp ^ (((n>>1)&3)<<2)),  kp = (k%32)/2
__device__ unsigned g_Bf[32768];   // fwd  B[n][k] = W2[k][n]
__device__ unsigned g_Bb[32768];   // bwd  B[n][k] = W2[n][k]
__device__ unsigned g_W1i[4096];   // z1   B[n][k] = W1[k][n], K=32 pad
__device__ float g_W1xT[HID * DD];
__device__ unsigned short g_W3H[HID], g_W3L[HID];

__device__ __forceinline__ unsigned packh2(float a, float b) {
    __half2 h = __floats2half2_rn(a, b);
    return *(unsigned*)&h;
}
// fp16 hi/lo split of a pair of floats
__device__ __forceinline__ void split2h(float v0, float v1, unsigned& hi, unsigned& lo) {
    __half h0 = __float2half_rn(v0), h1 = __float2half_rn(v1);
    float r0 = v0 - __half2float(h0), r1 = v1 - __half2float(h1);
    hi = (unsigned)__half_as_ushort(h0) | ((unsigned)__half_as_ushort(h1) << 16);
    lo = (unsigned)__half_as_ushort(__float2half_rn(r0)) |
         ((unsigned)__half_as_ushort(__float2half_rn(r1)) << 16);
}

__device__ __forceinline__ unsigned su32(const void* p) {
    unsigned a;
    asm("{ .reg .u64 t; cvta.to.shared.u64 t, %1; cvt.u32.u64 %0, t; }" : "=r"(a) : "l"(p));
    return a;
}
#define CPA16(d, s) asm volatile("cp.async.cg.shared.global [%0], [%1], 16;" :: "r"(d), "l"(s))
#define CPC()       asm volatile("cp.async.commit_group;" ::: "memory")
#define CPW0()      asm volatile("cp.async.wait_group 0;" ::: "memory")

__device__ __forceinline__ void mma16816(float* c, const unsigned* a, unsigned b0, unsigned b1) {
    asm volatile(
        "mma.sync.aligned.m16n8k16.row.col.f32.f16.f16.f32 "
        "{%0,%1,%2,%3}, {%4,%5,%6,%7}, {%8,%9}, {%0,%1,%2,%3};"
        : "+f"(c[0]), "+f"(c[1]), "+f"(c[2]), "+f"(c[3])
        : "r"(a[0]), "r"(a[1]), "r"(a[2]), "r"(a[3]), "r"(b0), "r"(b1));
}

// ---- prep: bake fp16 weight images ----------------------------------------
__global__ void prep_kernel(const float* __restrict__ W1, const float* __restrict__ W2,
                            const float* __restrict__ W3) {
    const int t = blockIdx.x * 256 + threadIdx.x;   // 128 blocks x 256
    const int n = t >> 7, kp = t & 127, k = kp * 2;
    const int idx = (kp >> 4) * 4096 + n * 16 + ((kp & 15) ^ (((n >> 1) & 3) << 2));
    g_Bf[idx] = packh2(W2[k * 256 + n], W2[(k + 1) * 256 + n]);       // fwd
    g_Bb[idx] = packh2(W2[n * 256 + k], W2[n * 256 + k + 1]);         // bwd
    if (kp < 16) {
        float v0 = (k < 23) ? W1[k * 256 + n] : 0.0f;
        float v1 = (k + 1 < 23) ? W1[(k + 1) * 256 + n] : 0.0f;
        const int i2 = n * 16 + (kp ^ (((n >> 1) & 3) << 2));
        g_W1i[i2] = packh2(v0, v1);
    }
    if (kp < 6) g_W1xT[n * 6 + kp] = W1[(17 + kp) * 256 + n];
    if (kp == 0) {
        __half h = __float2half_rn(W3[n]);
        g_W3H[n] = __half_as_ushort(h);
        g_W3L[n] = __half_as_ushort(__float2half_rn(W3[n] - __half2float(h)));
    }
}

// ---- shared memory --------------------------------------------------------
// A images (fp16 hi + fp16 residual): [m][kp], idx = m*128 + (kp ^ ((m&7)<<2))
struct __align__(16) SM {
    unsigned Ah[16384], Al[16384];          // 64KB + 64KB
    unsigned Bbuf[2][4096];                 // double-buffered 16KB chunks
    float X[2][128 * 6];
    float s[128 * 6];
    float scratch[128 * 6 * 4];             // spart
    float W1xT[256 * 6];
    float b1[256], b2[256];
    float logp[128];
    float gamma[4];
    unsigned short W3H[256], W3L[256];
};

extern __shared__ char smraw[];

__device__ __forceinline__ void issue_chunk(SM* sm, int buf,
                                            const unsigned* __restrict__ gB,
                                            int ch, int tid) {
    const unsigned dB = su32(sm->Bbuf[buf]);
    const char* sB = (const char*)(gB + ch * 4096);
    for (int i = tid; i < 1024; i += 512)
        CPA16(dB + i * 16, sB + i * 16);
    CPC();
}

// Double-buffered GEMM: M=128, N=256, K = 32*NCHUNK, fp16 2-pass (AhB + AlB).
// Single barrier per chunk: wait(ch) -> bar -> issue(ch+1) -> compute(ch).
template <int NCHUNK>
__device__ __forceinline__ void gemm_mma(SM* sm, const unsigned* __restrict__ gB,
                                         float acc[2][8][4], int m0, int n0,
                                         int lane, int tid) {
#pragma unroll
    for (int i = 0; i < 2; i++)
#pragma unroll
        for (int j = 0; j < 8; j++)
#pragma unroll
            for (int e = 0; e < 4; e++) acc[i][j][e] = 0.0f;
    const int swA = (lane >> 2) << 2;

    issue_chunk(sm, 0, gB, 0, tid);
    for (int ch = 0; ch < NCHUNK; ch++) {
        CPW0();                     // chunk ch landed (own copies)
        __syncthreads();            // all copies visible; prior readers done
        if (ch + 1 < NCHUNK) issue_chunk(sm, (ch + 1) & 1, gB, ch + 1, tid);
        const unsigned* B = sm->Bbuf[ch & 1];
#pragma unroll
        for (int ks = 0; ks < 2; ks++) {
            const int kpb = ch * 16 + ks * 8 + (lane & 3);
            const int kpl = ks * 8 + (lane & 3);
            unsigned afH[2][4], afL[2][4];
#pragma unroll
            for (int mt = 0; mt < 2; mt++) {
                const int r = m0 + mt * 16 + (lane >> 2);
                afH[mt][0] = sm->Ah[r * 128 + (kpb ^ swA)];
                afH[mt][1] = sm->Ah[(r + 8) * 128 + (kpb ^ swA)];
                afH[mt][2] = sm->Ah[r * 128 + ((kpb + 4) ^ swA)];
                afH[mt][3] = sm->Ah[(r + 8) * 128 + ((kpb + 4) ^ swA)];
                afL[mt][0] = sm->Al[r * 128 + (kpb ^ swA)];
                afL[mt][1] = sm->Al[(r + 8) * 128 + (kpb ^ swA)];
                afL[mt][2] = sm->Al[r * 128 + ((kpb + 4) ^ swA)];
                afL[mt][3] = sm->Al[(r + 8) * 128 + ((kpb + 4) ^ swA)];
            }
#pragma unroll
            for (int nt = 0; nt < 8; nt++) {
                const int n = n0 + nt * 8 + (lane >> 2);
                const int swb = ((n >> 1) & 3) << 2;
                const unsigned b0 = B[n * 16 + (kpl ^ swb)];
                const unsigned b1 = B[n * 16 + ((kpl + 4) ^ swb)];
                mma16816(acc[0][nt], afH[0], b0, b1);
                mma16816(acc[1][nt], afH[1], b0, b1);
                mma16816(acc[0][nt], afL[0], b0, b1);
                mma16816(acc[1][nt], afL[1], b0, b1);
            }
        }
    }
    __syncthreads();                // A-image readers done before epilogue writes
}

__global__ void __launch_bounds__(512, 1) svgd_kernel(
    const float* __restrict__ g_obs, const float* __restrict__ g_a,
    const float* __restrict__ g_b1, const float* __restrict__ g_b2,
    float* __restrict__ g_out)
{
    SM* sm = (SM*)smraw;
    const int tid = threadIdx.x, bx = blockIdx.x;
    const int warp = tid >> 5, lane = tid & 31;
    const int m0 = (warp & 3) * 32;          // warp row tile
    const int wN = warp >> 2;                // warp col group
    const int n0 = wN * 64;
    const int swA = (lane >> 2) << 2;

    // ---- prologue ---------------------------------------------------------
    if (tid < 256) {
        sm->b1[tid] = g_b1[tid];
        sm->b2[tid] = g_b2[tid];
        sm->W3H[tid] = g_W3H[tid];
        sm->W3L[tid] = g_W3L[tid];
    }
    for (int i = tid; i < 1536; i += 512) sm->W1xT[i] = g_W1xT[i];
    for (int i = tid; i < 768; i += 512) sm->X[0][i] = g_a[bx * 768 + i];
    if (tid < 128) sm->logp[tid] = 0.0f;
    __syncthreads();

    int cur = 0;
    float acc[2][8][4];
    unsigned mk[2];

    for (int step = 0; step < NSTEPS; step++) {
        // ---- build z1 A image: obs + X + pad (kp 0..15), hi/lo ----------
        for (int idx = tid; idx < 128 * 16; idx += 512) {
            const int row = idx >> 4, kp = idx & 15, k0 = kp * 2;
            float v0, v1;
            v0 = (k0 < NOBS) ? g_obs[(bx * 128 + row) * NOBS + k0]
               : (k0 < 23)   ? sm->X[cur][row * 6 + k0 - NOBS] : 0.0f;
            const int k1 = k0 + 1;
            v1 = (k1 < NOBS) ? g_obs[(bx * 128 + row) * NOBS + k1]
               : (k1 < 23)   ? sm->X[cur][row * 6 + k1 - NOBS] : 0.0f;
            unsigned hi, lo;
            split2h(v0, v1, hi, lo);
            const int o = row * 128 + (kp ^ ((row & 7) << 2));
            sm->Ah[o] = hi; sm->Al[o] = lo;
        }
        // (gemm's first barrier orders these writes before MMA reads)

        // ---- z1 GEMM + epilogue: h1 = relu(z1+b1), mask, split ----------
        gemm_mma<1>(sm, g_W1i, acc, m0, n0, lane, tid);
        mk[0] = 0u; mk[1] = 0u;
#pragma unroll
        for (int mt = 0; mt < 2; mt++) {
            const int rA = m0 + mt * 16 + (lane >> 2);
#pragma unroll
            for (int nt = 0; nt < 8; nt++) {
                const int cA = n0 + nt * 8 + ((lane & 3) << 1);
                const int kp = cA >> 1;
                float h0 = fmaxf(acc[mt][nt][0] + sm->b1[cA], 0.0f);
                float h1 = fmaxf(acc[mt][nt][1] + sm->b1[cA + 1], 0.0f);
                float h2 = fmaxf(acc[mt][nt][2] + sm->b1[cA], 0.0f);
                float h3 = fmaxf(acc[mt][nt][3] + sm->b1[cA + 1], 0.0f);
                if (h0 > 0.0f) mk[mt] |= 1u << (nt * 4 + 0);
                if (h1 > 0.0f) mk[mt] |= 1u << (nt * 4 + 1);
                if (h2 > 0.0f) mk[mt] |= 1u << (nt * 4 + 2);
                if (h3 > 0.0f) mk[mt] |= 1u << (nt * 4 + 3);
                unsigned hi, lo;
                split2h(h0, h1, hi, lo);
                int o = rA * 128 + (kp ^ swA);
                sm->Ah[o] = hi; sm->Al[o] = lo;
                split2h(h2, h3, hi, lo);
                o = (rA + 8) * 128 + (kp ^ swA);
                sm->Ah[o] = hi; sm->Al[o] = lo;
            }
        }

        // ---- fwd GEMM (z2) + epilogue: dz2 = (z2+b2>0)*W3 (hi/lo) -------
        gemm_mma<8>(sm, g_Bf, acc, m0, n0, lane, tid);
#pragma unroll
        for (int mt = 0; mt < 2; mt++) {
            const int rA = m0 + mt * 16 + (lane >> 2);
#pragma unroll
            for (int nt = 0; nt < 8; nt++) {
                const int cA = n0 + nt * 8 + ((lane & 3) << 1);
                const int kp = cA >> 1;
                const bool s0 = acc[mt][nt][0] + sm->b2[cA] > 0.0f;
                const bool s1 = acc[mt][nt][1] + sm->b2[cA + 1] > 0.0f;
                const bool s2 = acc[mt][nt][2] + sm->b2[cA] > 0.0f;
                const bool s3 = acc[mt][nt][3] + sm->b2[cA + 1] > 0.0f;
                const unsigned h0 = s0 ? sm->W3H[cA] : 0, h1 = s1 ? sm->W3H[cA + 1] : 0;
                const unsigned h2 = s2 ? sm->W3H[cA] : 0, h3 = s3 ? sm->W3H[cA + 1] : 0;
                const unsigned l0 = s0 ? sm->W3L[cA] : 0, l1 = s1 ? sm->W3L[cA + 1] : 0;
                const unsigned l2 = s2 ? sm->W3L[cA] : 0, l3 = s3 ? sm->W3L[cA + 1] : 0;
                int o = rA * 128 + (kp ^ swA);
                sm->Ah[o] = h0 | (h1 << 16); sm->Al[o] = l0 | (l1 << 16);
                o = (rA + 8) * 128 + (kp ^ swA);
                sm->Ah[o] = h2 | (h3 << 16); sm->Al[o] = l2 | (l3 << 16);
            }
        }

        // ---- bwd GEMM (dz1) + epilogue: mask + fold score matmul --------
        gemm_mma<8>(sm, g_Bb, acc, m0, n0, lane, tid);
        {
            float sp[4][6];
#pragma unroll
            for (int s = 0; s < 4; s++)
#pragma unroll
                for (int d = 0; d < 6; d++) sp[s][d] = 0.0f;
#pragma unroll
            for (int mt = 0; mt < 2; mt++)
#pragma unroll
                for (int nt = 0; nt < 8; nt++)
#pragma unroll
                    for (int e = 0; e < 4; e++) {
                        const float v = ((mk[mt] >> (nt * 4 + e)) & 1u)
                                            ? acc[mt][nt][e] : 0.0f;
                        const int c = n0 + nt * 8 + ((lane & 3) << 1) + (e & 1);
                        const int s = mt * 2 + (e >> 1);
                        const float* w = &sm->W1xT[c * 6];
#pragma unroll
                        for (int d = 0; d < 6; d++) sp[s][d] = fmaf(v, w[d], sp[s][d]);
                    }
#pragma unroll
            for (int s = 0; s < 4; s++)
#pragma unroll
                for (int d = 0; d < 6; d++) {
                    sp[s][d] += __shfl_xor_sync(0xFFFFFFFFu, sp[s][d], 1);
                    sp[s][d] += __shfl_xor_sync(0xFFFFFFFFu, sp[s][d], 2);
                }
            if ((lane & 3) == 0) {
#pragma unroll
                for (int s = 0; s < 4; s++) {
                    const int row = m0 + (s >> 1) * 16 + (s & 1) * 8 + (lane >> 2);
#pragma unroll
                    for (int d = 0; d < 6; d++)
                        sm->scratch[(row * 6 + d) * 4 + wN] = sp[s][d];
                }
            }
        }
        __syncthreads();
        for (int i = tid; i < 768; i += 512)
            sm->s[i] = sm->scratch[4 * i] + sm->scratch[4 * i + 1] +
                       sm->scratch[4 * i + 2] + sm->scratch[4 * i + 3];

        // ---- median: warp-local register bitonic sort (warps 0-3) -------
        // 512 elems = 496 upper-tri dists + inf pad; elem e = r*32 + lane.
        // Multiset median idx 511 of 1024 -> sorted-pairs idx 239 = (r7,l15).
        if (warp < 4) {
            const int g = warp;
            const float* Xg = &sm->X[cur][g * 192];
            float v[16];
#pragma unroll
            for (int r = 0; r < 16; r++) {
                const int e = r * 32 + lane;
                float val = __int_as_float(0x7f800000);
                if (e < 496) {
                    // triangular index -> (i,j): off(i) = i*(63-i)/2
                    int i = (int)((63.0f - sqrtf(3969.0f - 8.0f * (float)e)) * 0.5f);
                    int off = (i * (63 - i)) >> 1;
                    if (e < off) { i--; off = (i * (63 - i)) >> 1; }
                    else {
                        const int off2 = ((i + 1) * (62 - i)) >> 1;
                        if (e >= off2) { i++; off = off2; }
                    }
                    const int j = i + 1 + (e - off);
                    float ds = 0.0f;
#pragma unroll
                    for (int d = 0; d < 6; d++) {
                        const float dx = Xg[i * 6 + d] - Xg[j * 6 + d];
                        ds = fmaf(dx, dx, ds);
                    }
                    val = ds;
                }
                v[r] = val;
            }
#pragma unroll
            for (int k = 2; k <= 512; k <<= 1) {
#pragma unroll
                for (int j = k >> 1; j > 0; j >>= 1) {
                    if (j >= 32) {
                        const int rr = j >> 5;
#pragma unroll
                        for (int r = 0; r < 16; r++)
                            if (!(r & rr)) {
                                const int rp = r | rr;
                                const bool asc = ((r & (k >> 5)) == 0);
                                const float a = v[r], b = v[rp];
                                const float mn = fminf(a, b), mx = fmaxf(a, b);
                                v[r]  = asc ? mn : mx;
                                v[rp] = asc ? mx : mn;
                            }
                    } else {
#pragma unroll
                        for (int r = 0; r < 16; r++) {
                            const bool asc = (k >= 32) ? ((r & (k >> 5)) == 0)
                                                       : ((lane & k) == 0);
                            const float pv = __shfl_xor_sync(0xFFFFFFFFu, v[r], j);
                            const bool lower = ((lane & j) == 0);
                            const float mn = fminf(v[r], pv), mx = fmaxf(v[r], pv);
                            v[r] = (lower == asc) ? mn : mx;
                        }
                    }
                }
            }
            if (lane == 15) {
                const float hm = v[7] / (2.0f * LOG_NP1);
                sm->gamma[g] = 1.0f / (1e-8f + 2.0f * hm);
            }
        }
        __syncthreads();

        // ---- RBF phi / logp (4 warps per batch, 8 rows per warp) --------
        {
            const int g = warp >> 2, rb = (warp & 3) * 8;
            const float gamma = sm->gamma[g];
            const float* Xg = &sm->X[cur][g * 192];
            float* Xn = &sm->X[cur ^ 1][g * 192];
            const float* sg = &sm->s[g * 192];
            for (int ii = 0; ii < 8; ii++) {
                const int i = rb + ii, j = lane;
                float dx[6], red[8], ds = 0.0f, dsq = 0.0f;
#pragma unroll
                for (int d = 0; d < 6; d++) {
                    dx[d] = Xg[i * 6 + d] - Xg[j * 6 + d];
                    dsq = fmaf(dx[d], dx[d], dsq);
                }
                const float kap = __expf(-gamma * dsq);
#pragma unroll
                for (int d = 0; d < 6; d++) {
                    red[d] = kap * (sg[j * 6 + d] + 2.0f * gamma * dx[d]);
                    ds = fmaf(dx[d], sg[j * 6 + d], ds);
                }
                red[6] = -2.0f * gamma * kap * ds;
                red[7] = 2.0f * gamma * dsq * kap - 6.0f * kap;
#pragma unroll
                for (int q = 0; q < 8; q++)
#pragma unroll
                    for (int off = 16; off > 0; off >>= 1)
                        red[q] += __shfl_xor_sync(0xFFFFFFFFu, red[q], off);
                if (lane == 0) {
#pragma unroll
                    for (int d = 0; d < 6; d++) {
                        float xn = Xg[i * 6 + d] + LRATE * (red[d] * (1.0f / 32.0f));
                        Xn[i * 6 + d] = fminf(fmaxf(xn, -CLIP_LIM), CLIP_LIM);
                    }
                    const float l4 = red[6] * (1.0f / 32.0f);
                    const float l5 = -2.0f * gamma * (red[7] * (1.0f / 32.0f));
                    sm->logp[g * 32 + i] -= LRATE * (l4 + l5);
                }
            }
        }
        cur ^= 1;
        __syncthreads();
    }

    // ---- outputs ----------------------------------------------------------
    for (int i = tid; i < 768; i += 512) g_out[bx * 768 + i] = sm->X[cur][i];
    if (tid < 128) g_out[BATCH * NP * DD + bx * 128 + tid] = sm->logp[tid];
}

// ---------------------------------------------------------------------------
extern "C" void kernel_launch(void* const* d_in, const int* in_sizes, int n_in,
                              void* d_out, int out_size) {
    const float* obs = (const float*)d_in[0];
    const float* a   = (const float*)d_in[1];
    const float* W1  = (const float*)d_in[2];
    const float* b1  = (const float*)d_in[3];
    const float* W2  = (const float*)d_in[4];
    const float* b2  = (const float*)d_in[5];
    const float* W3  = (const float*)d_in[6];
    // d_in[7] = b3: unused (does not affect gradients/outputs)
    float* out = (float*)d_out;

    prep_kernel<<<128, 256>>>(W1, W2, W3);
    cudaFuncSetAttribute(svgd_kernel, cudaFuncAttributeMaxDynamicSharedMemorySize,
                         (int)sizeof(SM));
    svgd_kernel<<<512, 512, sizeof(SM)>>>(obs, a, b1, b2, out);
}

// round 13
// speedup vs baseline: 1.5306x; 1.1883x over previous
#include <cuda_runtime.h>
#include <cuda_fp16.h>
#include <stdint.h>
#include <math.h>

#define BATCH 2048
#define NP 32
#define DD 6
#define NOBS 17
#define HID 256
#define NSTEPS 10
#define LRATE 0.1f
#define CLIP_LIM 1.0f
#define LOG_NP1 3.49650756f

// ---- pre-baked B-operand images (fp16 pairs packed in u32, single image) --
// Layout: chunk c holds k in [32c,32c+32); within chunk: row n (0..255) of 16
// u32 units (unit = fp16 pair (k,k+1)); unit index swizzled:
//   idx = c*4096 + n*16 + (kp ^ (((n>>1)&3)<<2)),  kp = (k%32)/2
__device__ unsigned g_Bf[32768];   // fwd  B[n][k] = W2[k][n]
__device__ unsigned g_Bb[32768];   // bwd  B[n][k] = W2[n][k]
__device__ unsigned g_W1i[4096];   // z1   B[n][k] = W1[k][n], K=32 pad
__device__ float g_W1xT[HID * DD];
__device__ unsigned short g_W3H[HID], g_W3L[HID];

__device__ __forceinline__ unsigned packh2(float a, float b) {
    __half2 h = __floats2half2_rn(a, b);
    return *(unsigned*)&h;
}
// fp16 hi/lo split of a pair of floats
__device__ __forceinline__ void split2h(float v0, float v1, unsigned& hi, unsigned& lo) {
    __half h0 = __float2half_rn(v0), h1 = __float2half_rn(v1);
    float r0 = v0 - __half2float(h0), r1 = v1 - __half2float(h1);
    hi = (unsigned)__half_as_ushort(h0) | ((unsigned)__half_as_ushort(h1) << 16);
    lo = (unsigned)__half_as_ushort(__float2half_rn(r0)) |
         ((unsigned)__half_as_ushort(__float2half_rn(r1)) << 16);
}

__device__ __forceinline__ unsigned su32(const void* p) {
    unsigned a;
    asm("{ .reg .u64 t; cvta.to.shared.u64 t, %1; cvt.u32.u64 %0, t; }" : "=r"(a) : "l"(p));
    return a;
}
#define CPA16(d, s) asm volatile("cp.async.cg.shared.global [%0], [%1], 16;" :: "r"(d), "l"(s))
#define CPC()       asm volatile("cp.async.commit_group;" ::: "memory")
#define CPW0()      asm volatile("cp.async.wait_group 0;" ::: "memory")

__device__ __forceinline__ void mma16816(float* c, const unsigned* a, unsigned b0, unsigned b1) {
    asm volatile(
        "mma.sync.aligned.m16n8k16.row.col.f32.f16.f16.f32 "
        "{%0,%1,%2,%3}, {%4,%5,%6,%7}, {%8,%9}, {%0,%1,%2,%3};"
        : "+f"(c[0]), "+f"(c[1]), "+f"(c[2]), "+f"(c[3])
        : "r"(a[0]), "r"(a[1]), "r"(a[2]), "r"(a[3]), "r"(b0), "r"(b1));
}

// ---- prep: bake fp16 weight images ----------------------------------------
__global__ void prep_kernel(const float* __restrict__ W1, const float* __restrict__ W2,
                            const float* __restrict__ W3) {
    const int t = blockIdx.x * 256 + threadIdx.x;   // 128 blocks x 256
    const int n = t >> 7, kp = t & 127, k = kp * 2;
    const int idx = (kp >> 4) * 4096 + n * 16 + ((kp & 15) ^ (((n >> 1) & 3) << 2));
    g_Bf[idx] = packh2(W2[k * 256 + n], W2[(k + 1) * 256 + n]);       // fwd
    g_Bb[idx] = packh2(W2[n * 256 + k], W2[n * 256 + k + 1]);         // bwd
    if (kp < 16) {
        float v0 = (k < 23) ? W1[k * 256 + n] : 0.0f;
        float v1 = (k + 1 < 23) ? W1[(k + 1) * 256 + n] : 0.0f;
        const int i2 = n * 16 + (kp ^ (((n >> 1) & 3) << 2));
        g_W1i[i2] = packh2(v0, v1);
    }
    if (kp < 6) g_W1xT[n * 6 + kp] = W1[(17 + kp) * 256 + n];
    if (kp == 0) {
        __half h = __float2half_rn(W3[n]);
        g_W3H[n] = __half_as_ushort(h);
        g_W3L[n] = __half_as_ushort(__float2half_rn(W3[n] - __half2float(h)));
    }
}

// ---- shared memory (per CTA: 2 batches, M=64) ------------------------------
// A images: [m 0..63][unit kp 0..127], idx = m*128 + (kp ^ ((m&7)<<2))
// spart scratch ALIASES Bbuf: spart lives between bwd-GEMM's final barrier
// and the s-reduction; Bbuf's next write is next step's z1 issue_chunk,
// separated by barriers. Disjoint lifetimes.
struct __align__(16) SM {
    unsigned Ah[8192], Al[8192];            // 32KB + 32KB
    unsigned Bbuf[2][4096];                 // double-buffered 16KB chunks (+spart alias)
    float X[2][64 * 6];
    float s[64 * 6];
    float W1xT[256 * 6];
    float b1[256], b2[256];
    float logp[64];
    float gamma[2];
    unsigned short W3H[256], W3L[256];
};   // ~110.4KB -> 2 CTAs/SM

extern __shared__ char smraw[];

__device__ __forceinline__ void issue_chunk(SM* sm, int buf,
                                            const unsigned* __restrict__ gB,
                                            int ch, int tid) {
    const unsigned dB = su32(sm->Bbuf[buf]);
    const char* sB = (const char*)(gB + ch * 4096);
    for (int i = tid; i < 1024; i += 256)
        CPA16(dB + i * 16, sB + i * 16);
    CPC();
}

// Double-buffered GEMM: M=64, N=256, K = 32*NCHUNK, fp16 2-pass (AhB + AlB).
// Single barrier per chunk: wait(ch) -> bar -> issue(ch+1) -> compute(ch).
template <int NCHUNK>
__device__ __forceinline__ void gemm_mma(SM* sm, const unsigned* __restrict__ gB,
                                         float acc[2][8][4], int m0, int n0,
                                         int lane, int tid) {
#pragma unroll
    for (int i = 0; i < 2; i++)
#pragma unroll
        for (int j = 0; j < 8; j++)
#pragma unroll
            for (int e = 0; e < 4; e++) acc[i][j][e] = 0.0f;
    const int swA = (lane >> 2) << 2;

    issue_chunk(sm, 0, gB, 0, tid);
    for (int ch = 0; ch < NCHUNK; ch++) {
        CPW0();                     // chunk ch landed (own copies)
        __syncthreads();            // all copies visible; prior readers done
        if (ch + 1 < NCHUNK) issue_chunk(sm, (ch + 1) & 1, gB, ch + 1, tid);
        const unsigned* B = sm->Bbuf[ch & 1];
#pragma unroll
        for (int ks = 0; ks < 2; ks++) {
            const int kpb = ch * 16 + ks * 8 + (lane & 3);
            const int kpl = ks * 8 + (lane & 3);
            unsigned afH[2][4], afL[2][4];
#pragma unroll
            for (int mt = 0; mt < 2; mt++) {
                const int r = m0 + mt * 16 + (lane >> 2);
                afH[mt][0] = sm->Ah[r * 128 + (kpb ^ swA)];
                afH[mt][1] = sm->Ah[(r + 8) * 128 + (kpb ^ swA)];
                afH[mt][2] = sm->Ah[r * 128 + ((kpb + 4) ^ swA)];
                afH[mt][3] = sm->Ah[(r + 8) * 128 + ((kpb + 4) ^ swA)];
                afL[mt][0] = sm->Al[r * 128 + (kpb ^ swA)];
                afL[mt][1] = sm->Al[(r + 8) * 128 + (kpb ^ swA)];
                afL[mt][2] = sm->Al[r * 128 + ((kpb + 4) ^ swA)];
                afL[mt][3] = sm->Al[(r + 8) * 128 + ((kpb + 4) ^ swA)];
            }
#pragma unroll
            for (int nt = 0; nt < 8; nt++) {
                const int n = n0 + nt * 8 + (lane >> 2);
                const int swb = ((n >> 1) & 3) << 2;
                const unsigned b0 = B[n * 16 + (kpl ^ swb)];
                const unsigned b1 = B[n * 16 + ((kpl + 4) ^ swb)];
                mma16816(acc[0][nt], afH[0], b0, b1);
                mma16816(acc[1][nt], afH[1], b0, b1);
                mma16816(acc[0][nt], afL[0], b0, b1);
                mma16816(acc[1][nt], afL[1], b0, b1);
            }
        }
    }
    __syncthreads();                // A-image readers done before epilogue writes
}

__global__ void __launch_bounds__(256, 2) svgd_kernel(
    const float* __restrict__ g_obs, const float* __restrict__ g_a,
    const float* __restrict__ g_b1, const float* __restrict__ g_b2,
    float* __restrict__ g_out)
{
    SM* sm = (SM*)smraw;
    float* scratch = (float*)sm->Bbuf;       // spart alias (disjoint lifetime)
    const int tid = threadIdx.x, bx = blockIdx.x;
    const int warp = tid >> 5, lane = tid & 31;
    const int m0 = (warp & 1) * 32;          // warp row tile (M=64: 2 groups)
    const int wN = warp >> 1;                // warp col group (4 groups)
    const int n0 = wN * 64;
    const int swA = (lane >> 2) << 2;

    // ---- prologue ---------------------------------------------------------
    sm->b1[tid] = g_b1[tid];
    sm->b2[tid] = g_b2[tid];
    sm->W3H[tid] = g_W3H[tid];
    sm->W3L[tid] = g_W3L[tid];
    for (int i = tid; i < 1536; i += 256) sm->W1xT[i] = g_W1xT[i];
    for (int i = tid; i < 384; i += 256) sm->X[0][i] = g_a[bx * 384 + i];
    if (tid < 64) sm->logp[tid] = 0.0f;
    __syncthreads();

    int cur = 0;
    float acc[2][8][4];
    unsigned mk[2];

    for (int step = 0; step < NSTEPS; step++) {
        // ---- build z1 A image: obs + X + pad (kp 0..15), hi/lo ----------
        for (int idx = tid; idx < 64 * 16; idx += 256) {
            const int row = idx >> 4, kp = idx & 15, k0 = kp * 2;
            float v0, v1;
            v0 = (k0 < NOBS) ? g_obs[(bx * 64 + row) * NOBS + k0]
               : (k0 < 23)   ? sm->X[cur][row * 6 + k0 - NOBS] : 0.0f;
            const int k1 = k0 + 1;
            v1 = (k1 < NOBS) ? g_obs[(bx * 64 + row) * NOBS + k1]
               : (k1 < 23)   ? sm->X[cur][row * 6 + k1 - NOBS] : 0.0f;
            unsigned hi, lo;
            split2h(v0, v1, hi, lo);
            const int o = row * 128 + (kp ^ ((row & 7) << 2));
            sm->Ah[o] = hi; sm->Al[o] = lo;
        }
        // (gemm's first barrier orders these writes before MMA reads)

        // ---- z1 GEMM + epilogue: h1 = relu(z1+b1), mask, split ----------
        gemm_mma<1>(sm, g_W1i, acc, m0, n0, lane, tid);
        mk[0] = 0u; mk[1] = 0u;
#pragma unroll
        for (int mt = 0; mt < 2; mt++) {
            const int rA = m0 + mt * 16 + (lane >> 2);
#pragma unroll
            for (int nt = 0; nt < 8; nt++) {
                const int cA = n0 + nt * 8 + ((lane & 3) << 1);
                const int kp = cA >> 1;
                float h0 = fmaxf(acc[mt][nt][0] + sm->b1[cA], 0.0f);
                float h1 = fmaxf(acc[mt][nt][1] + sm->b1[cA + 1], 0.0f);
                float h2 = fmaxf(acc[mt][nt][2] + sm->b1[cA], 0.0f);
                float h3 = fmaxf(acc[mt][nt][3] + sm->b1[cA + 1], 0.0f);
                if (h0 > 0.0f) mk[mt] |= 1u << (nt * 4 + 0);
                if (h1 > 0.0f) mk[mt] |= 1u << (nt * 4 + 1);
                if (h2 > 0.0f) mk[mt] |= 1u << (nt * 4 + 2);
                if (h3 > 0.0f) mk[mt] |= 1u << (nt * 4 + 3);
                unsigned hi, lo;
                split2h(h0, h1, hi, lo);
                int o = rA * 128 + (kp ^ swA);
                sm->Ah[o] = hi; sm->Al[o] = lo;
                split2h(h2, h3, hi, lo);
                o = (rA + 8) * 128 + (kp ^ swA);
                sm->Ah[o] = hi; sm->Al[o] = lo;
            }
        }

        // ---- fwd GEMM (z2) + epilogue: dz2 = (z2+b2>0)*W3 (hi/lo) -------
        gemm_mma<8>(sm, g_Bf, acc, m0, n0, lane, tid);
#pragma unroll
        for (int mt = 0; mt < 2; mt++) {
            const int rA = m0 + mt * 16 + (lane >> 2);
#pragma unroll
            for (int nt = 0; nt < 8; nt++) {
                const int cA = n0 + nt * 8 + ((lane & 3) << 1);
                const int kp = cA >> 1;
                const bool s0 = acc[mt][nt][0] + sm->b2[cA] > 0.0f;
                const bool s1 = acc[mt][nt][1] + sm->b2[cA + 1] > 0.0f;
                const bool s2 = acc[mt][nt][2] + sm->b2[cA] > 0.0f;
                const bool s3 = acc[mt][nt][3] + sm->b2[cA + 1] > 0.0f;
                const unsigned h0 = s0 ? sm->W3H[cA] : 0, h1 = s1 ? sm->W3H[cA + 1] : 0;
                const unsigned h2 = s2 ? sm->W3H[cA] : 0, h3 = s3 ? sm->W3H[cA + 1] : 0;
                const unsigned l0 = s0 ? sm->W3L[cA] : 0, l1 = s1 ? sm->W3L[cA + 1] : 0;
                const unsigned l2 = s2 ? sm->W3L[cA] : 0, l3 = s3 ? sm->W3L[cA + 1] : 0;
                int o = rA * 128 + (kp ^ swA);
                sm->Ah[o] = h0 | (h1 << 16); sm->Al[o] = l0 | (l1 << 16);
                o = (rA + 8) * 128 + (kp ^ swA);
                sm->Ah[o] = h2 | (h3 << 16); sm->Al[o] = l2 | (l3 << 16);
            }
        }

        // ---- bwd GEMM (dz1) + epilogue: mask + fold score matmul --------
        gemm_mma<8>(sm, g_Bb, acc, m0, n0, lane, tid);
        {
            float sp[4][6];
#pragma unroll
            for (int s = 0; s < 4; s++)
#pragma unroll
                for (int d = 0; d < 6; d++) sp[s][d] = 0.0f;
#pragma unroll
            for (int mt = 0; mt < 2; mt++)
#pragma unroll
                for (int nt = 0; nt < 8; nt++)
#pragma unroll
                    for (int e = 0; e < 4; e++) {
                        const float v = ((mk[mt] >> (nt * 4 + e)) & 1u)
                                            ? acc[mt][nt][e] : 0.0f;
                        const int c = n0 + nt * 8 + ((lane & 3) << 1) + (e & 1);
                        const int s = mt * 2 + (e >> 1);
                        const float* w = &sm->W1xT[c * 6];
#pragma unroll
                        for (int d = 0; d < 6; d++) sp[s][d] = fmaf(v, w[d], sp[s][d]);
                    }
#pragma unroll
            for (int s = 0; s < 4; s++)
#pragma unroll
                for (int d = 0; d < 6; d++) {
                    sp[s][d] += __shfl_xor_sync(0xFFFFFFFFu, sp[s][d], 1);
                    sp[s][d] += __shfl_xor_sync(0xFFFFFFFFu, sp[s][d], 2);
                }
            if ((lane & 3) == 0) {
#pragma unroll
                for (int s = 0; s < 4; s++) {
                    const int row = m0 + (s >> 1) * 16 + (s & 1) * 8 + (lane >> 2);
#pragma unroll
                    for (int d = 0; d < 6; d++)
                        scratch[(row * 6 + d) * 4 + wN] = sp[s][d];
                }
            }
        }
        __syncthreads();
        for (int i = tid; i < 384; i += 256)
            sm->s[i] = scratch[4 * i] + scratch[4 * i + 1] +
                       scratch[4 * i + 2] + scratch[4 * i + 3];

        // ---- median: warp-local register bitonic sort (warps 0-1) -------
        // 512 elems = 496 upper-tri dists + inf pad; elem e = r*32 + lane.
        // Multiset median idx 511 of 1024 -> sorted-pairs idx 239 = (r7,l15).
        if (warp < 2) {
            const int g = warp;
            const float* Xg = &sm->X[cur][g * 192];
            float v[16];
#pragma unroll
            for (int r = 0; r < 16; r++) {
                const int e = r * 32 + lane;
                float val = __int_as_float(0x7f800000);
                if (e < 496) {
                    // triangular index -> (i,j): off(i) = i*(63-i)/2
                    int i = (int)((63.0f - sqrtf(3969.0f - 8.0f * (float)e)) * 0.5f);
                    int off = (i * (63 - i)) >> 1;
                    if (e < off) { i--; off = (i * (63 - i)) >> 1; }
                    else {
                        const int off2 = ((i + 1) * (62 - i)) >> 1;
                        if (e >= off2) { i++; off = off2; }
                    }
                    const int j = i + 1 + (e - off);
                    float ds = 0.0f;
#pragma unroll
                    for (int d = 0; d < 6; d++) {
                        const float dx = Xg[i * 6 + d] - Xg[j * 6 + d];
                        ds = fmaf(dx, dx, ds);
                    }
                    val = ds;
                }
                v[r] = val;
            }
#pragma unroll
            for (int k = 2; k <= 512; k <<= 1) {
#pragma unroll
                for (int j = k >> 1; j > 0; j >>= 1) {
                    if (j >= 32) {
                        const int rr = j >> 5;
#pragma unroll
                        for (int r = 0; r < 16; r++)
                            if (!(r & rr)) {
                                const int rp = r | rr;
                                const bool asc = ((r & (k >> 5)) == 0);
                                const float a = v[r], b = v[rp];
                                const float mn = fminf(a, b), mx = fmaxf(a, b);
                                v[r]  = asc ? mn : mx;
                                v[rp] = asc ? mx : mn;
                            }
                    } else {
#pragma unroll
                        for (int r = 0; r < 16; r++) {
                            const bool asc = (k >= 32) ? ((r & (k >> 5)) == 0)
                                                       : ((lane & k) == 0);
                            const float pv = __shfl_xor_sync(0xFFFFFFFFu, v[r], j);
                            const bool lower = ((lane & j) == 0);
                            const float mn = fminf(v[r], pv), mx = fmaxf(v[r], pv);
                            v[r] = (lower == asc) ? mn : mx;
                        }
                    }
                }
            }
            if (lane == 15) {
                const float hm = v[7] / (2.0f * LOG_NP1);
                sm->gamma[g] = 1.0f / (1e-8f + 2.0f * hm);
            }
        }
        __syncthreads();

        // ---- RBF phi / logp (4 warps per batch, 8 rows per warp) --------
        {
            const int g = warp >> 2, rb = (warp & 3) * 8;
            const float gamma = sm->gamma[g];
            const float* Xg = &sm->X[cur][g * 192];
            float* Xn = &sm->X[cur ^ 1][g * 192];
            const float* sg = &sm->s[g * 192];
            for (int ii = 0; ii < 8; ii++) {
                const int i = rb + ii, j = lane;
                float dx[6], red[8], ds = 0.0f, dsq = 0.0f;
#pragma unroll
                for (int d = 0; d < 6; d++) {
                    dx[d] = Xg[i * 6 + d] - Xg[j * 6 + d];
                    dsq = fmaf(dx[d], dx[d], dsq);
                }
                const float kap = __expf(-gamma * dsq);
#pragma unroll
                for (int d = 0; d < 6; d++) {
                    red[d] = kap * (sg[j * 6 + d] + 2.0f * gamma * dx[d]);
                    ds = fmaf(dx[d], sg[j * 6 + d], ds);
                }
                red[6] = -2.0f * gamma * kap * ds;
                red[7] = 2.0f * gamma * dsq * kap - 6.0f * kap;
#pragma unroll
                for (int q = 0; q < 8; q++)
#pragma unroll
                    for (int off = 16; off > 0; off >>= 1)
                        red[q] += __shfl_xor_sync(0xFFFFFFFFu, red[q], off);
                if (lane == 0) {
#pragma unroll
                    for (int d = 0; d < 6; d++) {
                        float xn = Xg[i * 6 + d] + LRATE * (red[d] * (1.0f / 32.0f));
                        Xn[i * 6 + d] = fminf(fmaxf(xn, -CLIP_LIM), CLIP_LIM);
                    }
                    const float l4 = red[6] * (1.0f / 32.0f);
                    const float l5 = -2.0f * gamma * (red[7] * (1.0f / 32.0f));
                    sm->logp[g * 32 + i] -= LRATE * (l4 + l5);
                }
            }
        }
        cur ^= 1;
        __syncthreads();
    }

    // ---- outputs ----------------------------------------------------------
    for (int i = tid; i < 384; i += 256) g_out[bx * 384 + i] = sm->X[cur][i];
    if (tid < 64) g_out[BATCH * NP * DD + bx * 64 + tid] = sm->logp[tid];
}

// ---------------------------------------------------------------------------
extern "C" void kernel_launch(void* const* d_in, const int* in_sizes, int n_in,
                              void* d_out, int out_size) {
    const float* obs = (const float*)d_in[0];
    const float* a   = (const float*)d_in[1];
    const float* W1  = (const float*)d_in[2];
    const float* b1  = (const float*)d_in[3];
    const float* W2  = (const float*)d_in[4];
    const float* b2  = (const float*)d_in[5];
    const float* W3  = (const float*)d_in[6];
    // d_in[7] = b3: unused (does not affect gradients/outputs)
    float* out = (float*)d_out;

    prep_kernel<<<128, 256>>>(W1, W2, W3);
    cudaFuncSetAttribute(svgd_kernel, cudaFuncAttributeMaxDynamicSharedMemorySize,
                         (int)sizeof(SM));
    svgd_kernel<<<1024, 256, sizeof(SM)>>>(obs, a, b1, b2, out);
}

// round 14
// speedup vs baseline: 2.0113x; 1.3141x over previous
#include <cuda_runtime.h>
#include <cuda_fp16.h>
#include <stdint.h>
#include <math.h>

#define BATCH 2048
#define NP 32
#define DD 6
#define NOBS 17
#define HID 256
#define NSTEPS 10
#define LRATE 0.1f
#define CLIP_LIM 1.0f
#define LOG_NP1 3.49650756f

// ---- pre-baked B-operand images (fp16 pairs packed in u32, single image) --
// chunk c holds k in [32c,32c+32); within chunk: row n (0..255) of 16 u32
// units (unit = fp16 pair (k,k+1)); idx = c*4096 + n*16 + (kp ^ (((n>>1)&3)<<2))
__device__ unsigned g_Bf[32768];   // fwd  B[n][k] = W2[k][n]
__device__ unsigned g_Bb[32768];   // bwd  B[n][k] = W2[n][k]
__device__ unsigned g_W1i[4096];   // z1   B[n][k] = W1[k][n], K=32 pad
__device__ float g_W1xT[HID * DD];
__device__ unsigned short g_W3h[HID];

__device__ __forceinline__ unsigned packh2(float a, float b) {
    __half2 h = __floats2half2_rn(a, b);
    return *(unsigned*)&h;
}

__device__ __forceinline__ unsigned su32(const void* p) {
    unsigned a;
    asm("{ .reg .u64 t; cvta.to.shared.u64 t, %1; cvt.u32.u64 %0, t; }" : "=r"(a) : "l"(p));
    return a;
}
#define CPA16(d, s) asm volatile("cp.async.cg.shared.global [%0], [%1], 16;" :: "r"(d), "l"(s))
#define CPC()       asm volatile("cp.async.commit_group;" ::: "memory")
#define CPW0()      asm volatile("cp.async.wait_group 0;" ::: "memory")

__device__ __forceinline__ void mma16816(float* c, const unsigned* a, unsigned b0, unsigned b1) {
    asm volatile(
        "mma.sync.aligned.m16n8k16.row.col.f32.f16.f16.f32 "
        "{%0,%1,%2,%3}, {%4,%5,%6,%7}, {%8,%9}, {%0,%1,%2,%3};"
        : "+f"(c[0]), "+f"(c[1]), "+f"(c[2]), "+f"(c[3])
        : "r"(a[0]), "r"(a[1]), "r"(a[2]), "r"(a[3]), "r"(b0), "r"(b1));
}

// ---- prep: bake fp16 weight images ----------------------------------------
__global__ void prep_kernel(const float* __restrict__ W1, const float* __restrict__ W2,
                            const float* __restrict__ W3) {
    const int t = blockIdx.x * 256 + threadIdx.x;   // 128 blocks x 256
    const int n = t >> 7, kp = t & 127, k = kp * 2;
    const int idx = (kp >> 4) * 4096 + n * 16 + ((kp & 15) ^ (((n >> 1) & 3) << 2));
    g_Bf[idx] = packh2(W2[k * 256 + n], W2[(k + 1) * 256 + n]);       // fwd
    g_Bb[idx] = packh2(W2[n * 256 + k], W2[n * 256 + k + 1]);         // bwd
    if (kp < 16) {
        float v0 = (k < 23) ? W1[k * 256 + n] : 0.0f;
        float v1 = (k + 1 < 23) ? W1[(k + 1) * 256 + n] : 0.0f;
        const int i2 = n * 16 + (kp ^ (((n >> 1) & 3) << 2));
        g_W1i[i2] = packh2(v0, v1);
    }
    if (kp < 6) g_W1xT[n * 6 + kp] = W1[(17 + kp) * 256 + n];
    if (kp == 0) g_W3h[n] = __half_as_ushort(__float2half_rn(W3[n]));
}

// ---- shared memory (per CTA: 2 batches, M=64) ------------------------------
// A image (fp16, single): [m 0..63][unit kp 0..127], idx = m*128 + (kp ^ ((m&7)<<2))
// spart scratch ALIASES Bbuf (disjoint lifetimes, barrier-separated).
struct __align__(16) SM {
    unsigned Ah[8192];                      // 32KB
    unsigned Bbuf[2][4096];                 // double-buffered 16KB chunks (+spart alias)
    float X[2][64 * 6];
    float s[64 * 6];
    float W1xT[256 * 6];
    float b1[256], b2[256];
    float logp[64];
    float gamma[2];
    unsigned short W3h[256];
};   // ~78KB -> 2 CTAs/SM

extern __shared__ char smraw[];

__device__ __forceinline__ void issue_chunk(SM* sm, int buf,
                                            const unsigned* __restrict__ gB,
                                            int ch, int tid) {
    const unsigned dB = su32(sm->Bbuf[buf]);
    const char* sB = (const char*)(gB + ch * 4096);
    for (int i = tid; i < 1024; i += 256)
        CPA16(dB + i * 16, sB + i * 16);
    CPC();
}

// Double-buffered GEMM: M=64, N=256, K = 32*NCHUNK, fp16 single-pass.
// Single barrier per chunk: wait(ch) -> bar -> issue(ch+1) -> compute(ch).
template <int NCHUNK>
__device__ __forceinline__ void gemm_mma(SM* sm, const unsigned* __restrict__ gB,
                                         float acc[2][8][4], int m0, int n0,
                                         int lane, int tid) {
#pragma unroll
    for (int i = 0; i < 2; i++)
#pragma unroll
        for (int j = 0; j < 8; j++)
#pragma unroll
            for (int e = 0; e < 4; e++) acc[i][j][e] = 0.0f;
    const int swA = (lane >> 2) << 2;

    issue_chunk(sm, 0, gB, 0, tid);
    for (int ch = 0; ch < NCHUNK; ch++) {
        CPW0();                     // chunk ch landed (own copies)
        __syncthreads();            // all copies visible; prior readers done
        if (ch + 1 < NCHUNK) issue_chunk(sm, (ch + 1) & 1, gB, ch + 1, tid);
        const unsigned* B = sm->Bbuf[ch & 1];
#pragma unroll
        for (int ks = 0; ks < 2; ks++) {
            const int kpb = ch * 16 + ks * 8 + (lane & 3);
            const int kpl = ks * 8 + (lane & 3);
            unsigned af[2][4];
#pragma unroll
            for (int mt = 0; mt < 2; mt++) {
                const int r = m0 + mt * 16 + (lane >> 2);
                af[mt][0] = sm->Ah[r * 128 + (kpb ^ swA)];
                af[mt][1] = sm->Ah[(r + 8) * 128 + (kpb ^ swA)];
                af[mt][2] = sm->Ah[r * 128 + ((kpb + 4) ^ swA)];
                af[mt][3] = sm->Ah[(r + 8) * 128 + ((kpb + 4) ^ swA)];
            }
#pragma unroll
            for (int nt = 0; nt < 8; nt++) {
                const int n = n0 + nt * 8 + (lane >> 2);
                const int swb = ((n >> 1) & 3) << 2;
                const unsigned b0 = B[n * 16 + (kpl ^ swb)];
                const unsigned b1 = B[n * 16 + ((kpl + 4) ^ swb)];
                mma16816(acc[0][nt], af[0], b0, b1);
                mma16816(acc[1][nt], af[1], b0, b1);
            }
        }
    }
    __syncthreads();                // A-image readers done before epilogue writes
}

__global__ void __launch_bounds__(256, 2) svgd_kernel(
    const float* __restrict__ g_obs, const float* __restrict__ g_a,
    const float* __restrict__ g_b1, const float* __restrict__ g_b2,
    float* __restrict__ g_out)
{
    SM* sm = (SM*)smraw;
    float* scratch = (float*)sm->Bbuf;       // spart alias (disjoint lifetime)
    const int tid = threadIdx.x, bx = blockIdx.x;
    const int warp = tid >> 5, lane = tid & 31;
    const int m0 = (warp & 1) * 32;          // warp row tile (M=64: 2 groups)
    const int wN = warp >> 1;                // warp col group (4 groups)
    const int n0 = wN * 64;
    const int swA = (lane >> 2) << 2;

    // ---- prologue ---------------------------------------------------------
    sm->b1[tid] = g_b1[tid];
    sm->b2[tid] = g_b2[tid];
    sm->W3h[tid] = g_W3h[tid];
    for (int i = tid; i < 1536; i += 256) sm->W1xT[i] = g_W1xT[i];
    for (int i = tid; i < 384; i += 256) sm->X[0][i] = g_a[bx * 384 + i];
    if (tid < 64) sm->logp[tid] = 0.0f;
    __syncthreads();

    int cur = 0;
    float acc[2][8][4];
    unsigned mk[2];

    for (int step = 0; step < NSTEPS; step++) {
        // ---- build z1 A image: obs + X + pad (kp 0..15), fp16 -----------
        for (int idx = tid; idx < 64 * 16; idx += 256) {
            const int row = idx >> 4, kp = idx & 15, k0 = kp * 2;
            float v0, v1;
            v0 = (k0 < NOBS) ? g_obs[(bx * 64 + row) * NOBS + k0]
               : (k0 < 23)   ? sm->X[cur][row * 6 + k0 - NOBS] : 0.0f;
            const int k1 = k0 + 1;
            v1 = (k1 < NOBS) ? g_obs[(bx * 64 + row) * NOBS + k1]
               : (k1 < 23)   ? sm->X[cur][row * 6 + k1 - NOBS] : 0.0f;
            sm->Ah[row * 128 + (kp ^ ((row & 7) << 2))] = packh2(v0, v1);
        }
        // (gemm's first barrier orders these writes before MMA reads)

        // ---- z1 GEMM + epilogue: h1 = relu(z1+b1), mask, fp16 -----------
        gemm_mma<1>(sm, g_W1i, acc, m0, n0, lane, tid);
        mk[0] = 0u; mk[1] = 0u;
#pragma unroll
        for (int mt = 0; mt < 2; mt++) {
            const int rA = m0 + mt * 16 + (lane >> 2);
#pragma unroll
            for (int nt = 0; nt < 8; nt++) {
                const int cA = n0 + nt * 8 + ((lane & 3) << 1);
                const int kp = cA >> 1;
                float h0 = fmaxf(acc[mt][nt][0] + sm->b1[cA], 0.0f);
                float h1 = fmaxf(acc[mt][nt][1] + sm->b1[cA + 1], 0.0f);
                float h2 = fmaxf(acc[mt][nt][2] + sm->b1[cA], 0.0f);
                float h3 = fmaxf(acc[mt][nt][3] + sm->b1[cA + 1], 0.0f);
                if (h0 > 0.0f) mk[mt] |= 1u << (nt * 4 + 0);
                if (h1 > 0.0f) mk[mt] |= 1u << (nt * 4 + 1);
                if (h2 > 0.0f) mk[mt] |= 1u << (nt * 4 + 2);
                if (h3 > 0.0f) mk[mt] |= 1u << (nt * 4 + 3);
                sm->Ah[rA * 128 + (kp ^ swA)] = packh2(h0, h1);
                sm->Ah[(rA + 8) * 128 + (kp ^ swA)] = packh2(h2, h3);
            }
        }

        // ---- fwd GEMM (z2) + epilogue: dz2 = (z2+b2>0)*W3, fp16 ---------
        gemm_mma<8>(sm, g_Bf, acc, m0, n0, lane, tid);
#pragma unroll
        for (int mt = 0; mt < 2; mt++) {
            const int rA = m0 + mt * 16 + (lane >> 2);
#pragma unroll
            for (int nt = 0; nt < 8; nt++) {
                const int cA = n0 + nt * 8 + ((lane & 3) << 1);
                const int kp = cA >> 1;
                const unsigned w0 = (acc[mt][nt][0] + sm->b2[cA] > 0.0f)
                                        ? (unsigned)sm->W3h[cA] : 0u;
                const unsigned w1 = (acc[mt][nt][1] + sm->b2[cA + 1] > 0.0f)
                                        ? (unsigned)sm->W3h[cA + 1] : 0u;
                const unsigned w2 = (acc[mt][nt][2] + sm->b2[cA] > 0.0f)
                                        ? (unsigned)sm->W3h[cA] : 0u;
                const unsigned w3 = (acc[mt][nt][3] + sm->b2[cA + 1] > 0.0f)
                                        ? (unsigned)sm->W3h[cA + 1] : 0u;
                sm->Ah[rA * 128 + (kp ^ swA)] = w0 | (w1 << 16);
                sm->Ah[(rA + 8) * 128 + (kp ^ swA)] = w2 | (w3 << 16);
            }
        }

        // ---- bwd GEMM (dz1) + epilogue: mask + fold score matmul --------
        gemm_mma<8>(sm, g_Bb, acc, m0, n0, lane, tid);
        {
            float sp[4][6];
#pragma unroll
            for (int s = 0; s < 4; s++)
#pragma unroll
                for (int d = 0; d < 6; d++) sp[s][d] = 0.0f;
#pragma unroll
            for (int mt = 0; mt < 2; mt++)
#pragma unroll
                for (int nt = 0; nt < 8; nt++)
#pragma unroll
                    for (int e = 0; e < 4; e++) {
                        const float v = ((mk[mt] >> (nt * 4 + e)) & 1u)
                                            ? acc[mt][nt][e] : 0.0f;
                        const int c = n0 + nt * 8 + ((lane & 3) << 1) + (e & 1);
                        const int s = mt * 2 + (e >> 1);
                        const float* w = &sm->W1xT[c * 6];
#pragma unroll
                        for (int d = 0; d < 6; d++) sp[s][d] = fmaf(v, w[d], sp[s][d]);
                    }
#pragma unroll
            for (int s = 0; s < 4; s++)
#pragma unroll
                for (int d = 0; d < 6; d++) {
                    sp[s][d] += __shfl_xor_sync(0xFFFFFFFFu, sp[s][d], 1);
                    sp[s][d] += __shfl_xor_sync(0xFFFFFFFFu, sp[s][d], 2);
                }
            if ((lane & 3) == 0) {
#pragma unroll
                for (int s = 0; s < 4; s++) {
                    const int row = m0 + (s >> 1) * 16 + (s & 1) * 8 + (lane >> 2);
#pragma unroll
                    for (int d = 0; d < 6; d++)
                        scratch[(row * 6 + d) * 4 + wN] = sp[s][d];
                }
            }
        }
        __syncthreads();
        for (int i = tid; i < 384; i += 256)
            sm->s[i] = scratch[4 * i] + scratch[4 * i + 1] +
                       scratch[4 * i + 2] + scratch[4 * i + 3];

        // ---- median: warp-local register bitonic sort (warps 0-1) -------
        // 512 elems = 496 upper-tri dists + inf pad; elem e = r*32 + lane.
        // Multiset median idx 511 of 1024 -> sorted-pairs idx 239 = (r7,l15).
        if (warp < 2) {
            const int g = warp;
            const float* Xg = &sm->X[cur][g * 192];
            float v[16];
#pragma unroll
            for (int r = 0; r < 16; r++) {
                const int e = r * 32 + lane;
                float val = __int_as_float(0x7f800000);
                if (e < 496) {
                    // triangular index -> (i,j): off(i) = i*(63-i)/2
                    int i = (int)((63.0f - sqrtf(3969.0f - 8.0f * (float)e)) * 0.5f);
                    int off = (i * (63 - i)) >> 1;
                    if (e < off) { i--; off = (i * (63 - i)) >> 1; }
                    else {
                        const int off2 = ((i + 1) * (62 - i)) >> 1;
                        if (e >= off2) { i++; off = off2; }
                    }
                    const int j = i + 1 + (e - off);
                    float ds = 0.0f;
#pragma unroll
                    for (int d = 0; d < 6; d++) {
                        const float dx = Xg[i * 6 + d] - Xg[j * 6 + d];
                        ds = fmaf(dx, dx, ds);
                    }
                    val = ds;
                }
                v[r] = val;
            }
#pragma unroll
            for (int k = 2; k <= 512; k <<= 1) {
#pragma unroll
                for (int j = k >> 1; j > 0; j >>= 1) {
                    if (j >= 32) {
                        const int rr = j >> 5;
#pragma unroll
                        for (int r = 0; r < 16; r++)
                            if (!(r & rr)) {
                                const int rp = r | rr;
                                const bool asc = ((r & (k >> 5)) == 0);
                                const float a = v[r], b = v[rp];
                                const float mn = fminf(a, b), mx = fmaxf(a, b);
                                v[r]  = asc ? mn : mx;
                                v[rp] = asc ? mx : mn;
                            }
                    } else {
#pragma unroll
                        for (int r = 0; r < 16; r++) {
                            const bool asc = (k >= 32) ? ((r & (k >> 5)) == 0)
                                                       : ((lane & k) == 0);
                            const float pv = __shfl_xor_sync(0xFFFFFFFFu, v[r], j);
                            const bool lower = ((lane & j) == 0);
                            const float mn = fminf(v[r], pv), mx = fmaxf(v[r], pv);
                            v[r] = (lower == asc) ? mn : mx;
                        }
                    }
                }
            }
            if (lane == 15) {
                const float hm = v[7] / (2.0f * LOG_NP1);
                sm->gamma[g] = 1.0f / (1e-8f + 2.0f * hm);
            }
        }
        __syncthreads();

        // ---- RBF phi / logp (4 warps per batch, 8 rows per warp) --------
        {
            const int g = warp >> 2, rb = (warp & 3) * 8;
            const float gamma = sm->gamma[g];
            const float* Xg = &sm->X[cur][g * 192];
            float* Xn = &sm->X[cur ^ 1][g * 192];
            const float* sg = &sm->s[g * 192];
            for (int ii = 0; ii < 8; ii++) {
                const int i = rb + ii, j = lane;
                float dx[6], red[8], ds = 0.0f, dsq = 0.0f;
#pragma unroll
                for (int d = 0; d < 6; d++) {
                    dx[d] = Xg[i * 6 + d] - Xg[j * 6 + d];
                    dsq = fmaf(dx[d], dx[d], dsq);
                }
                const float kap = __expf(-gamma * dsq);
#pragma unroll
                for (int d = 0; d < 6; d++) {
                    red[d] = kap * (sg[j * 6 + d] + 2.0f * gamma * dx[d]);
                    ds = fmaf(dx[d], sg[j * 6 + d], ds);
                }
                red[6] = -2.0f * gamma * kap * ds;
                red[7] = 2.0f * gamma * dsq * kap - 6.0f * kap;
#pragma unroll
                for (int q = 0; q < 8; q++)
#pragma unroll
                    for (int off = 16; off > 0; off >>= 1)
                        red[q] += __shfl_xor_sync(0xFFFFFFFFu, red[q], off);
                if (lane == 0) {
#pragma unroll
                    for (int d = 0; d < 6; d++) {
                        float xn = Xg[i * 6 + d] + LRATE * (red[d] * (1.0f / 32.0f));
                        Xn[i * 6 + d] = fminf(fmaxf(xn, -CLIP_LIM), CLIP_LIM);
                    }
                    const float l4 = red[6] * (1.0f / 32.0f);
                    const float l5 = -2.0f * gamma * (red[7] * (1.0f / 32.0f));
                    sm->logp[g * 32 + i] -= LRATE * (l4 + l5);
                }
            }
        }
        cur ^= 1;
        __syncthreads();
    }

    // ---- outputs ----------------------------------------------------------
    for (int i = tid; i < 384; i += 256) g_out[bx * 384 + i] = sm->X[cur][i];
    if (tid < 64) g_out[BATCH * NP * DD + bx * 64 + tid] = sm->logp[tid];
}

// ---------------------------------------------------------------------------
extern "C" void kernel_launch(void* const* d_in, const int* in_sizes, int n_in,
                              void* d_out, int out_size) {
    const float* obs = (const float*)d_in[0];
    const float* a   = (const float*)d_in[1];
    const float* W1  = (const float*)d_in[2];
    const float* b1  = (const float*)d_in[3];
    const float* W2  = (const float*)d_in[4];
    const float* b2  = (const float*)d_in[5];
    const float* W3  = (const float*)d_in[6];
    // d_in[7] = b3: unused (does not affect gradients/outputs)
    float* out = (float*)d_out;

    prep_kernel<<<128, 256>>>(W1, W2, W3);
    cudaFuncSetAttribute(svgd_kernel, cudaFuncAttributeMaxDynamicSharedMemorySize,
                         (int)sizeof(SM));
    svgd_kernel<<<1024, 256, sizeof(SM)>>>(obs, a, b1, b2, out);
}